// round 6
// baseline (speedup 1.0000x reference)
#include <cuda_runtime.h>
#include <cuda_fp16.h>
#include <cstdint>
#include <cstddef>

#define NSEQ  2048
#define CDIM  64
#define CH    512
#define JD    4096
#define BTOT  16
#define ROWS_TOT (BTOT * NSEQ)
#define EPS_F 1e-5f
#define SCALE_F 256.0f          // operand pre-scale (2^8)

// stage (k64): A hi 128x64 fp16 =16KB, A lo 16KB, B hi 256x64 fp16 =32KB
#define STAGE_BYTES 65536
#define SMEM_DYN (3 * STAGE_BYTES)

// ---------------- scratch ----------------
__device__ __half g_QtH[(size_t)BTOT * CH * NSEQ];   // [b][i][n], x256
__device__ __half g_QtL[(size_t)BTOT * CH * NSEQ];
__device__ __half g_KtH[(size_t)BTOT * CH * NSEQ];   // [b][j][n], x256 (hi only)
__device__ __half g_VH[(size_t)BTOT * NSEQ * CH];    // [b][n][c], x256
__device__ __half g_VL[(size_t)BTOT * NSEQ * CH];
__device__ float  g_S[(size_t)BTOT * CH * JD];       // scores, x2^16
__device__ __half g_AH[(size_t)BTOT * CH * JD];      // attn fp16 [b][i][j]
__device__ float  g_CTX[(size_t)BTOT * NSEQ * CH];   // true scale
__device__ double g_red[BTOT * 2];
__device__ float  g_rstd[BTOT];                      // rsqrt(var+eps)/2^16

// ---------------- helpers ----------------
__device__ __forceinline__ uint32_t smem_u32(const void* p) {
    uint32_t a;
    asm("{ .reg .u64 t; cvta.to.shared.u64 t, %1; cvt.u32.u64 %0, t; }" : "=r"(a) : "l"(p));
    return a;
}
__device__ __forceinline__ void cp_async16(uint32_t s, const void* g) {
    asm volatile("cp.async.cg.shared.global [%0], [%1], 16;" :: "r"(s), "l"(g) : "memory");
}
__device__ __forceinline__ void cp_commit() {
    asm volatile("cp.async.commit_group;" ::: "memory");
}
template <int N>
__device__ __forceinline__ void cp_wait_group() {
    asm volatile("cp.async.wait_group %0;" :: "n"(N) : "memory");
}
// SW128 swizzle for 128-byte rows
__device__ __forceinline__ uint32_t swz(uint32_t off) {
    return off ^ ((off >> 3) & 0x70);
}
__device__ __forceinline__ void mma16816h(float* c, const uint32_t a[4],
                                          uint32_t b0, uint32_t b1) {
    asm volatile(
        "mma.sync.aligned.m16n8k16.row.col.f32.f16.f16.f32 "
        "{%0,%1,%2,%3}, {%4,%5,%6,%7}, {%8,%9}, {%0,%1,%2,%3};"
        : "+f"(c[0]), "+f"(c[1]), "+f"(c[2]), "+f"(c[3])
        : "r"(a[0]), "r"(a[1]), "r"(a[2]), "r"(a[3]), "r"(b0), "r"(b1));
}
__device__ __forceinline__ void ldsm4(uint32_t r[4], uint32_t addr) {
    asm volatile("ldmatrix.sync.aligned.m8n8.x4.shared.b16 {%0,%1,%2,%3}, [%4];"
                 : "=r"(r[0]), "=r"(r[1]), "=r"(r[2]), "=r"(r[3]) : "r"(addr));
}

// load ROWS x 64 fp16 tile (128B rows) into SW128-swizzled smem
template <int ROWS>
__device__ __forceinline__ void ldtile(uint32_t sdst, const char* g, size_t stride, int tid) {
#pragma unroll
    for (int t = 0; t < ROWS / 32; t++) {
        int op = tid + t * 256;
        int row = op >> 3, c = op & 7;
        uint32_t off = row * 128 + c * 16;
        cp_async16(sdst + swz(off), g + (size_t)row * stride + c * 16);
    }
}

// ============================================================================
// 2-term fp16 compute for one k64 stage; warp tile 64x64 (4 mt x 8 nt)
// stage: Ah @0 (16KB), Al @16KB, Bh @32KB (32KB). ldmatrix fragment loads.
// rowA[mt]/rowB[np] are per-lane byte offsets (row*128 + (lane>>4)*16).
// ============================================================================
__device__ __forceinline__ void compute_stage(uint32_t sb, const uint32_t rowA[4],
                                              const uint32_t rowB[4],
                                              float acc[4][8][4]) {
    uint32_t sA = sb, sAl = sb + 16384, sB = sb + 32768;
#pragma unroll
    for (int kk = 0; kk < 4; kk++) {
        uint32_t kb = kk * 32;
        uint32_t ah[4][4], al[4][4], bf[4][4];
#pragma unroll
        for (int mt = 0; mt < 4; mt++) {
            uint32_t so = swz(rowA[mt] + kb);
            ldsm4(ah[mt], sA + so);
            ldsm4(al[mt], sAl + so);
        }
#pragma unroll
        for (int np = 0; np < 4; np++)
            ldsm4(bf[np], sB + swz(rowB[np] + kb));
#pragma unroll
        for (int np = 0; np < 4; np++) {
#pragma unroll
            for (int h = 0; h < 2; h++) {
                uint32_t b0 = bf[np][h], b1 = bf[np][2 + h];
                int nt = np * 2 + h;
#pragma unroll
                for (int mt = 0; mt < 4; mt++) {
                    mma16816h(acc[mt][nt], ah[mt], b0, b1);
                    mma16816h(acc[mt][nt], al[mt], b0, b1);
                }
            }
        }
    }
}

// ============================================================================
// scores: S[ob][i][j] = sum_n Qt[ob][i][n] * Kt[kvb][jc][n]   (x 2^16)
// CTA tile 128(i) x 256(j), grid (16, 4, 16), block 256
// Fused per-batch sum/sumsq into g_red.
// ============================================================================
__global__ void __launch_bounds__(256, 1) scores_mma() {
    extern __shared__ char dsm[];
    uint32_t sb = smem_u32(dsm);
    __shared__ double sred[8], sred2[8];

    int ob = blockIdx.z;
    int kvbase = (ob < 8) ? 8 : 0;
    int i0 = blockIdx.y << 7;
    int j0 = blockIdx.x << 8;
    int kvb = kvbase + (j0 >> 9);
    int jc0 = j0 & 511;

    int tid = threadIdx.x;
    int wid = tid >> 5, lane = tid & 31;
    int g = lane >> 2, tg = lane & 3;
    int wm = (wid & 1) * 64, wn = (wid >> 1) * 64;

    uint32_t rowA[4], rowB[4];
    uint32_t lrow = lane & 15, lcol = (lane >> 4) * 16;
#pragma unroll
    for (int mt = 0; mt < 4; mt++) rowA[mt] = (wm + mt * 16 + lrow) * 128 + lcol;
#pragma unroll
    for (int np = 0; np < 4; np++) rowB[np] = (wn + np * 16 + lrow) * 128 + lcol;

    const char* AhB = (const char*)g_QtH + ((size_t)ob * CH + i0) * NSEQ * 2;
    const char* AlB = (const char*)g_QtL + ((size_t)ob * CH + i0) * NSEQ * 2;
    const char* BhB = (const char*)g_KtH + ((size_t)kvb * CH + jc0) * NSEQ * 2;
    const size_t st = NSEQ * 2;

    float acc[4][8][4];
#pragma unroll
    for (int a = 0; a < 4; a++)
#pragma unroll
        for (int b = 0; b < 8; b++)
#pragma unroll
            for (int c = 0; c < 4; c++) acc[a][b][c] = 0.f;

    const int NCH = NSEQ / 64;   // 32

    auto load_chunk = [&](int c, int stg) {
        uint32_t s = sb + stg * STAGE_BYTES;
        size_t ko = (size_t)c * 128;
        ldtile<128>(s,         AhB + ko, st, tid);
        ldtile<128>(s + 16384, AlB + ko, st, tid);
        ldtile<256>(s + 32768, BhB + ko, st, tid);
        cp_commit();
    };

    load_chunk(0, 0);
    load_chunk(1, 1);
    for (int c = 0; c < NCH; c++) {
        if (c + 1 < NCH) cp_wait_group<1>(); else cp_wait_group<0>();
        __syncthreads();
        if (c + 2 < NCH) load_chunk(c + 2, (c + 2) % 3);
        compute_stage(sb + (c % 3) * STAGE_BYTES, rowA, rowB, acc);
    }

    // write scores + fused sum/sumsq
    float* gout = g_S + (size_t)ob * CH * JD;
    float s1 = 0.f, s2 = 0.f;
#pragma unroll
    for (int mt = 0; mt < 4; mt++) {
#pragma unroll
        for (int nt = 0; nt < 8; nt++) {
            int row = i0 + wm + mt * 16 + g;
            int col = j0 + wn + nt * 8 + tg * 2;
            float v0 = acc[mt][nt][0], v1 = acc[mt][nt][1];
            float v2 = acc[mt][nt][2], v3 = acc[mt][nt][3];
            *(float2*)&gout[(size_t)row * JD + col] = make_float2(v0, v1);
            *(float2*)&gout[(size_t)(row + 8) * JD + col] = make_float2(v2, v3);
            s1 += v0 + v1 + v2 + v3;
            s2 += v0 * v0 + v1 * v1 + v2 * v2 + v3 * v3;
        }
    }
    double d1 = (double)s1, d2 = (double)s2;
    for (int off = 16; off > 0; off >>= 1) {
        d1 += __shfl_down_sync(0xffffffffu, d1, off);
        d2 += __shfl_down_sync(0xffffffffu, d2, off);
    }
    if (lane == 0) { sred[wid] = d1; sred2[wid] = d2; }
    __syncthreads();
    if (tid == 0) {
        double t1 = 0.0, t2 = 0.0;
#pragma unroll
        for (int w = 0; w < 8; w++) { t1 += sred[w]; t2 += sred2[w]; }
        atomicAdd(&g_red[2 * ob], t1);
        atomicAdd(&g_red[2 * ob + 1], t2);
    }
}

// ============================================================================
// ctx: CTX[ob][n][i] = sum_j V[kvb(j)][n][jc] * attn[ob][i][j]
// CTA tile 128(n) x 256(i), grid (2, 16, 16), block 256
// ============================================================================
__global__ void __launch_bounds__(256, 1) ctx_mma() {
    extern __shared__ char dsm[];
    uint32_t sb = smem_u32(dsm);

    int ob = blockIdx.z;
    int kvbase = (ob < 8) ? 8 : 0;
    int i0 = blockIdx.x << 8;
    int n0 = blockIdx.y << 7;

    int tid = threadIdx.x;
    int wid = tid >> 5, lane = tid & 31;
    int g = lane >> 2, tg = lane & 3;
    int wm = (wid & 1) * 64, wn = (wid >> 1) * 64;

    uint32_t rowA[4], rowB[4];
    uint32_t lrow = lane & 15, lcol = (lane >> 4) * 16;
#pragma unroll
    for (int mt = 0; mt < 4; mt++) rowA[mt] = (wm + mt * 16 + lrow) * 128 + lcol;
#pragma unroll
    for (int np = 0; np < 4; np++) rowB[np] = (wn + np * 16 + lrow) * 128 + lcol;

    const char* BhB = (const char*)g_AH + ((size_t)ob * CH + i0) * JD * 2;

    float acc[4][8][4];
#pragma unroll
    for (int a = 0; a < 4; a++)
#pragma unroll
        for (int b = 0; b < 8; b++)
#pragma unroll
            for (int c = 0; c < 4; c++) acc[a][b][c] = 0.f;

    const int NCH = JD / 64;   // 64

    auto load_chunk = [&](int c, int stg) {
        uint32_t s = sb + stg * STAGE_BYTES;
        int j0c = c * 64;
        int kvb = kvbase + (j0c >> 9);
        int jc0 = j0c & 511;
        const char* Ahp = (const char*)g_VH + (((size_t)kvb * NSEQ + n0) * CH + jc0) * 2;
        const char* Alp = (const char*)g_VL + (((size_t)kvb * NSEQ + n0) * CH + jc0) * 2;
        ldtile<128>(s,         Ahp, CH * 2, tid);
        ldtile<128>(s + 16384, Alp, CH * 2, tid);
        ldtile<256>(s + 32768, BhB + (size_t)j0c * 2, JD * 2, tid);
        cp_commit();
    };

    load_chunk(0, 0);
    load_chunk(1, 1);
    for (int c = 0; c < NCH; c++) {
        if (c + 1 < NCH) cp_wait_group<1>(); else cp_wait_group<0>();
        __syncthreads();
        if (c + 2 < NCH) load_chunk(c + 2, (c + 2) % 3);
        compute_stage(sb + (c % 3) * STAGE_BYTES, rowA, rowB, acc);
    }

    const float ds = 1.0f / SCALE_F;   // undo V pre-scale
    float* gout = g_CTX + (size_t)ob * NSEQ * CH;
#pragma unroll
    for (int mt = 0; mt < 4; mt++) {
#pragma unroll
        for (int nt = 0; nt < 8; nt++) {
            int row = n0 + wm + mt * 16 + g;
            int col = i0 + wn + nt * 8 + tg * 2;
            *(float2*)&gout[(size_t)row * CH + col] =
                make_float2(acc[mt][nt][0] * ds, acc[mt][nt][1] * ds);
            *(float2*)&gout[(size_t)(row + 8) * CH + col] =
                make_float2(acc[mt][nt][2] * ds, acc[mt][nt][3] * ds);
        }
    }
}

// ============================================================================
// projection GEMM: C = A[32768,64] @ B[64,512], scaled x256, split fp16 hi(/lo).
// transposed=1 -> out[b][col][n], else out[m][col]. OL may be null (hi only).
// ============================================================================
__global__ void __launch_bounds__(256) proj_gemm(const float* __restrict__ A,
                                                 const float* __restrict__ Bm,
                                                 __half* __restrict__ OH,
                                                 __half* __restrict__ OL,
                                                 int transposed) {
    __shared__ __align__(16) float As[16][68];
    __shared__ __align__(16) float Bs[16][64];
    const int K = CDIM, N = CH;
    int bm = blockIdx.y * 64, bn = blockIdx.x * 64;
    int tid = threadIdx.x;
    int tx = tid & 15, ty = tid >> 4;
    int am = tid >> 2, ak = (tid & 3) << 2;
    int br = tid >> 4, bc = (tid & 15) << 2;
    const float* Aptr = A + (size_t)(bm + am) * K + ak;

    float acc[4][4];
#pragma unroll
    for (int i = 0; i < 4; i++)
#pragma unroll
        for (int j = 0; j < 4; j++) acc[i][j] = 0.f;

    for (int k0 = 0; k0 < K; k0 += 16) {
        float4 av = *(const float4*)(Aptr + k0);
        As[ak + 0][am] = av.x; As[ak + 1][am] = av.y;
        As[ak + 2][am] = av.z; As[ak + 3][am] = av.w;
        *(float4*)&Bs[br][bc] = *(const float4*)&Bm[(size_t)(k0 + br) * N + bn + bc];
        __syncthreads();
#pragma unroll
        for (int kk = 0; kk < 16; kk++) {
            float a0 = As[kk][ty * 4 + 0], a1 = As[kk][ty * 4 + 1];
            float a2 = As[kk][ty * 4 + 2], a3 = As[kk][ty * 4 + 3];
            float b0 = Bs[kk][tx * 4 + 0], b1 = Bs[kk][tx * 4 + 1];
            float b2 = Bs[kk][tx * 4 + 2], b3 = Bs[kk][tx * 4 + 3];
            acc[0][0] += a0 * b0; acc[0][1] += a0 * b1; acc[0][2] += a0 * b2; acc[0][3] += a0 * b3;
            acc[1][0] += a1 * b0; acc[1][1] += a1 * b1; acc[1][2] += a1 * b2; acc[1][3] += a1 * b3;
            acc[2][0] += a2 * b0; acc[2][1] += a2 * b1; acc[2][2] += a2 * b2; acc[2][3] += a2 * b3;
            acc[3][0] += a3 * b0; acc[3][1] += a3 * b1; acc[3][2] += a3 * b2; acc[3][3] += a3 * b3;
        }
        __syncthreads();
    }

    if (transposed) {
        int b = bm >> 11;
        int nloc = (bm & 2047) + ty * 4;
#pragma unroll
        for (int j = 0; j < 4; j++) {
            int col = bn + tx * 4 + j;
            union { __half v[4]; uint2 u; } ph, pl;
#pragma unroll
            for (int i = 0; i < 4; i++) {
                float f = acc[i][j] * SCALE_F;
                __half h = __float2half(f);
                ph.v[i] = h;
                pl.v[i] = __float2half(f - __half2float(h));
            }
            size_t off = (size_t)b * (CH * NSEQ) + (size_t)col * NSEQ + nloc;
            *(uint2*)&OH[off] = ph.u;
            if (OL) *(uint2*)&OL[off] = pl.u;
        }
    } else {
#pragma unroll
        for (int i = 0; i < 4; i++) {
            int m = bm + ty * 4 + i;
            union { __half v[4]; uint2 u; } ph, pl;
#pragma unroll
            for (int j = 0; j < 4; j++) {
                float f = acc[i][j] * SCALE_F;
                __half h = __float2half(f);
                ph.v[j] = h;
                pl.v[j] = __float2half(f - __half2float(h));
            }
            size_t off = (size_t)m * CH + bn + tx * 4;
            *(uint2*)&OH[off] = ph.u;
            if (OL) *(uint2*)&OL[off] = pl.u;
        }
    }
}

// ============================================================================
// fp32 NN GEMM (out projection)
// ============================================================================
__global__ void __launch_bounds__(256) gemm_nn(const float* __restrict__ A,
                                               const float* __restrict__ Bm,
                                               float* __restrict__ Cm,
                                               int M, int N, int K) {
    __shared__ __align__(16) float As[16][68];
    __shared__ __align__(16) float Bs[16][64];
    int bm = blockIdx.y * 64, bn = blockIdx.x * 64;
    int tid = threadIdx.x;
    int tx = tid & 15, ty = tid >> 4;
    int am = tid >> 2, ak = (tid & 3) << 2;
    int br = tid >> 4, bc = (tid & 15) << 2;
    const float* Aptr = A + (size_t)(bm + am) * K + ak;

    float acc[4][4];
#pragma unroll
    for (int i = 0; i < 4; i++)
#pragma unroll
        for (int j = 0; j < 4; j++) acc[i][j] = 0.f;

    for (int k0 = 0; k0 < K; k0 += 16) {
        float4 av = *(const float4*)(Aptr + k0);
        As[ak + 0][am] = av.x; As[ak + 1][am] = av.y;
        As[ak + 2][am] = av.z; As[ak + 3][am] = av.w;
        *(float4*)&Bs[br][bc] = *(const float4*)&Bm[(size_t)(k0 + br) * N + bn + bc];
        __syncthreads();
#pragma unroll
        for (int kk = 0; kk < 16; kk++) {
            float a0 = As[kk][ty * 4 + 0], a1 = As[kk][ty * 4 + 1];
            float a2 = As[kk][ty * 4 + 2], a3 = As[kk][ty * 4 + 3];
            float b0 = Bs[kk][tx * 4 + 0], b1 = Bs[kk][tx * 4 + 1];
            float b2 = Bs[kk][tx * 4 + 2], b3 = Bs[kk][tx * 4 + 3];
            acc[0][0] += a0 * b0; acc[0][1] += a0 * b1; acc[0][2] += a0 * b2; acc[0][3] += a0 * b3;
            acc[1][0] += a1 * b0; acc[1][1] += a1 * b1; acc[1][2] += a1 * b2; acc[1][3] += a1 * b3;
            acc[2][0] += a2 * b0; acc[2][1] += a2 * b1; acc[2][2] += a2 * b2; acc[2][3] += a2 * b3;
            acc[3][0] += a3 * b0; acc[3][1] += a3 * b1; acc[3][2] += a3 * b2; acc[3][3] += a3 * b3;
        }
        __syncthreads();
    }
#pragma unroll
    for (int i = 0; i < 4; i++) {
        float4 v = make_float4(acc[i][0], acc[i][1], acc[i][2], acc[i][3]);
        *(float4*)&Cm[(size_t)(bm + ty * 4 + i) * N + bn + tx * 4] = v;
    }
}

// ============================================================================
// instance-norm finalize + softmax
// ============================================================================
__global__ void zero_red_k() {
    int t = threadIdx.x;
    if (t < BTOT) { g_red[2 * t] = 0.0; g_red[2 * t + 1] = 0.0; }
}

__global__ void finalize_k() {
    int t = threadIdx.x;
    if (t < BTOT) {
        const double SC = 65536.0;   // scores are scaled by 2^16
        double n = (double)CH * (double)JD;
        double mean = g_red[2 * t] / (n * SC);
        double var  = g_red[2 * t + 1] / (n * SC * SC) - mean * mean;
        g_rstd[t] = rsqrtf((float)var + EPS_F) / (float)SC;
    }
}

__global__ void __launch_bounds__(256) softmax_k() {
    int row = blockIdx.x;
    int b = row >> 9;
    float rstd = g_rstd[b];          // already includes 1/2^16
    const float* p = g_S + (size_t)row * JD;
    __half* ah = g_AH + (size_t)row * JD;
    int t = threadIdx.x;

    float x[16];
    float mx = -1e30f;
#pragma unroll
    for (int u = 0; u < 16; u++) {
        x[u] = p[u * 256 + t] * rstd;
        mx = fmaxf(mx, x[u]);
    }
    __shared__ float red[8];
    for (int off = 16; off > 0; off >>= 1)
        mx = fmaxf(mx, __shfl_xor_sync(0xffffffffu, mx, off));
    int lane = t & 31, wid = t >> 5;
    if (lane == 0) red[wid] = mx;
    __syncthreads();
    float gm = red[0];
#pragma unroll
    for (int w = 1; w < 8; w++) gm = fmaxf(gm, red[w]);
    __syncthreads();

    float sum = 0.f;
#pragma unroll
    for (int u = 0; u < 16; u++) {
        x[u] = __expf(x[u] - gm);
        sum += x[u];
    }
    for (int off = 16; off > 0; off >>= 1)
        sum += __shfl_xor_sync(0xffffffffu, sum, off);
    if (lane == 0) red[wid] = sum;
    __syncthreads();
    float tot = 0.f;
#pragma unroll
    for (int w = 0; w < 8; w++) tot += red[w];
    float inv = 1.0f / tot;
#pragma unroll
    for (int u = 0; u < 16; u++)
        ah[u * 256 + t] = __float2half(x[u] * inv);
}

// ============================================================================
// launch
// ============================================================================
extern "C" void kernel_launch(void* const* d_in, const int* in_sizes, int n_in,
                              void* d_out, int out_size) {
    const float* emb = (const float*)d_in[0];
    const float* Wq  = (const float*)d_in[1];
    const float* Wk  = (const float*)d_in[2];
    const float* Wv  = (const float*)d_in[3];
    const float* Wo  = (const float*)d_in[4];
    float* outp = (float*)d_out;

    void *qh, *ql, *kh, *vh, *vl, *cx;
    cudaGetSymbolAddress(&qh, g_QtH);
    cudaGetSymbolAddress(&ql, g_QtL);
    cudaGetSymbolAddress(&kh, g_KtH);
    cudaGetSymbolAddress(&vh, g_VH);
    cudaGetSymbolAddress(&vl, g_VL);
    cudaGetSymbolAddress(&cx, g_CTX);

    cudaFuncSetAttribute(scores_mma, cudaFuncAttributeMaxDynamicSharedMemorySize, SMEM_DYN);
    cudaFuncSetAttribute(ctx_mma, cudaFuncAttributeMaxDynamicSharedMemorySize, SMEM_DYN);

    dim3 gproj(CH / 64, ROWS_TOT / 64);
    proj_gemm<<<gproj, 256>>>(emb, Wq, (__half*)qh, (__half*)ql, 1);
    proj_gemm<<<gproj, 256>>>(emb, Wk, (__half*)kh, (__half*)nullptr, 1);
    proj_gemm<<<gproj, 256>>>(emb, Wv, (__half*)vh, (__half*)vl, 0);

    zero_red_k<<<1, 32>>>();
    scores_mma<<<dim3(JD / 256, CH / 128, BTOT), 256, SMEM_DYN>>>();
    finalize_k<<<1, 32>>>();
    softmax_k<<<BTOT * CH, 256>>>();

    ctx_mma<<<dim3(CH / 256, NSEQ / 128, BTOT), 256, SMEM_DYN>>>();

    gemm_nn<<<dim3(CDIM / 64, ROWS_TOT / 64), 256>>>((const float*)cx, Wo, outp,
                                                     ROWS_TOT, CDIM, CH);
}

// round 7
// speedup vs baseline: 1.6103x; 1.6103x over previous
#include <cuda_runtime.h>
#include <cuda_fp16.h>
#include <cstdint>
#include <cstddef>

#define NSEQ  2048
#define CDIM  64
#define CH    512
#define JD    4096
#define BTOT  16
#define ROWS_TOT (BTOT * NSEQ)
#define EPS_F 1e-5f
#define SCALE_F 256.0f          // operand pre-scale (2^8)

// stage (k64): A 128x64 fp16 = 16KB, B 256x64 fp16 = 32KB
#define STAGE_BYTES 49152
#define NSTG 4
#define SMEM_DYN (NSTG * STAGE_BYTES)

// ---------------- scratch ----------------
__device__ __half g_Qt[(size_t)BTOT * CH * NSEQ];    // [b][i][n], x256
__device__ __half g_Kt[(size_t)BTOT * CH * NSEQ];    // [b][j][n], x256
__device__ __half g_V [(size_t)BTOT * NSEQ * CH];    // [b][n][c], x256
__device__ float  g_S [(size_t)BTOT * CH * JD];      // scores, x2^16
__device__ __half g_A [(size_t)BTOT * CH * JD];      // attn fp16 [b][i][j]
__device__ float  g_CTX[(size_t)BTOT * NSEQ * CH];   // true scale
__device__ double g_red[BTOT * 2];
__device__ float  g_rstd[BTOT];                      // rsqrt(var+eps)/2^16

// ---------------- helpers ----------------
__device__ __forceinline__ uint32_t smem_u32(const void* p) {
    uint32_t a;
    asm("{ .reg .u64 t; cvta.to.shared.u64 t, %1; cvt.u32.u64 %0, t; }" : "=r"(a) : "l"(p));
    return a;
}
__device__ __forceinline__ void cp_async16(uint32_t s, const void* g) {
    asm volatile("cp.async.cg.shared.global [%0], [%1], 16;" :: "r"(s), "l"(g) : "memory");
}
__device__ __forceinline__ void cp_commit() {
    asm volatile("cp.async.commit_group;" ::: "memory");
}
template <int N>
__device__ __forceinline__ void cp_wait_group() {
    asm volatile("cp.async.wait_group %0;" :: "n"(N) : "memory");
}
// SW128 swizzle for 128-byte rows
__device__ __forceinline__ uint32_t swz(uint32_t off) {
    return off ^ ((off >> 3) & 0x70);
}
__device__ __forceinline__ void mma16816h(float* c, const uint32_t a[4],
                                          uint32_t b0, uint32_t b1) {
    asm volatile(
        "mma.sync.aligned.m16n8k16.row.col.f32.f16.f16.f32 "
        "{%0,%1,%2,%3}, {%4,%5,%6,%7}, {%8,%9}, {%0,%1,%2,%3};"
        : "+f"(c[0]), "+f"(c[1]), "+f"(c[2]), "+f"(c[3])
        : "r"(a[0]), "r"(a[1]), "r"(a[2]), "r"(a[3]), "r"(b0), "r"(b1));
}
__device__ __forceinline__ void ldsm4(uint32_t r[4], uint32_t addr) {
    asm volatile("ldmatrix.sync.aligned.m8n8.x4.shared.b16 {%0,%1,%2,%3}, [%4];"
                 : "=r"(r[0]), "=r"(r[1]), "=r"(r[2]), "=r"(r[3]) : "r"(addr));
}

// load ROWS x 64 fp16 tile (128B rows) into SW128-swizzled smem
template <int ROWS>
__device__ __forceinline__ void ldtile(uint32_t sdst, const char* g, size_t stride, int tid) {
#pragma unroll
    for (int t = 0; t < ROWS / 32; t++) {
        int op = tid + t * 256;
        int row = op >> 3, c = op & 7;
        uint32_t off = row * 128 + c * 16;
        cp_async16(sdst + swz(off), g + (size_t)row * stride + c * 16);
    }
}

// ============================================================================
// single-term fp16 compute for one k64 stage; warp tile 64x64 (4 mt x 8 nt)
// stage: A @0 (16KB), B @16KB (32KB). ldmatrix fragment loads.
// ============================================================================
__device__ __forceinline__ void compute_stage(uint32_t sb, const uint32_t rowA[4],
                                              const uint32_t rowB[4],
                                              float acc[4][8][4]) {
    uint32_t sA = sb, sB = sb + 16384;
#pragma unroll
    for (int kk = 0; kk < 4; kk++) {
        uint32_t kb = kk * 32;
        uint32_t ah[4][4], bf[4][4];
#pragma unroll
        for (int mt = 0; mt < 4; mt++)
            ldsm4(ah[mt], sA + swz(rowA[mt] + kb));
#pragma unroll
        for (int np = 0; np < 4; np++)
            ldsm4(bf[np], sB + swz(rowB[np] + kb));
#pragma unroll
        for (int np = 0; np < 4; np++) {
#pragma unroll
            for (int h = 0; h < 2; h++) {
                uint32_t b0 = bf[np][h], b1 = bf[np][2 + h];
                int nt = np * 2 + h;
#pragma unroll
                for (int mt = 0; mt < 4; mt++)
                    mma16816h(acc[mt][nt], ah[mt], b0, b1);
            }
        }
    }
}

// ============================================================================
// scores: S[ob][i][j] = sum_n Qt[ob][i][n] * Kt[kvb][jc][n]   (x 2^16)
// CTA tile 128(i) x 256(j), grid (16, 4, 16), block 256
// Fused per-batch sum/sumsq into g_red.
// ============================================================================
__global__ void __launch_bounds__(256, 1) scores_mma() {
    extern __shared__ char dsm[];
    uint32_t sb = smem_u32(dsm);
    __shared__ double sred[8], sred2[8];

    int ob = blockIdx.z;
    int kvbase = (ob < 8) ? 8 : 0;
    int i0 = blockIdx.y << 7;
    int j0 = blockIdx.x << 8;
    int kvb = kvbase + (j0 >> 9);
    int jc0 = j0 & 511;

    int tid = threadIdx.x;
    int wid = tid >> 5, lane = tid & 31;
    int g = lane >> 2, tg = lane & 3;
    int wm = (wid & 1) * 64, wn = (wid >> 1) * 64;

    uint32_t rowA[4], rowB[4];
    uint32_t lrow = lane & 15, lcol = (lane >> 4) * 16;
#pragma unroll
    for (int mt = 0; mt < 4; mt++) rowA[mt] = (wm + mt * 16 + lrow) * 128 + lcol;
#pragma unroll
    for (int np = 0; np < 4; np++) rowB[np] = (wn + np * 16 + lrow) * 128 + lcol;

    const char* AB = (const char*)g_Qt + ((size_t)ob * CH + i0) * NSEQ * 2;
    const char* BB = (const char*)g_Kt + ((size_t)kvb * CH + jc0) * NSEQ * 2;
    const size_t st = NSEQ * 2;

    float acc[4][8][4];
#pragma unroll
    for (int a = 0; a < 4; a++)
#pragma unroll
        for (int b = 0; b < 8; b++)
#pragma unroll
            for (int c = 0; c < 4; c++) acc[a][b][c] = 0.f;

    const int NCH = NSEQ / 64;   // 32

    auto load_chunk = [&](int c, int stg) {
        uint32_t s = sb + stg * STAGE_BYTES;
        size_t ko = (size_t)c * 128;
        ldtile<128>(s,         AB + ko, st, tid);
        ldtile<256>(s + 16384, BB + ko, st, tid);
        cp_commit();
    };

    load_chunk(0, 0);
    load_chunk(1, 1);
    load_chunk(2, 2);
    for (int c = 0; c < NCH; c++) {
        if (c + 2 < NCH) cp_wait_group<2>();
        else if (c + 1 < NCH) cp_wait_group<1>();
        else cp_wait_group<0>();
        __syncthreads();
        if (c + 3 < NCH) load_chunk(c + 3, (c + 3) % NSTG);
        compute_stage(sb + (c % NSTG) * STAGE_BYTES, rowA, rowB, acc);
    }

    // write scores + fused sum/sumsq
    float* gout = g_S + (size_t)ob * CH * JD;
    float s1 = 0.f, s2 = 0.f;
#pragma unroll
    for (int mt = 0; mt < 4; mt++) {
#pragma unroll
        for (int nt = 0; nt < 8; nt++) {
            int row = i0 + wm + mt * 16 + g;
            int col = j0 + wn + nt * 8 + tg * 2;
            float v0 = acc[mt][nt][0], v1 = acc[mt][nt][1];
            float v2 = acc[mt][nt][2], v3 = acc[mt][nt][3];
            *(float2*)&gout[(size_t)row * JD + col] = make_float2(v0, v1);
            *(float2*)&gout[(size_t)(row + 8) * JD + col] = make_float2(v2, v3);
            s1 += v0 + v1 + v2 + v3;
            s2 += v0 * v0 + v1 * v1 + v2 * v2 + v3 * v3;
        }
    }
    double d1 = (double)s1, d2 = (double)s2;
    for (int off = 16; off > 0; off >>= 1) {
        d1 += __shfl_down_sync(0xffffffffu, d1, off);
        d2 += __shfl_down_sync(0xffffffffu, d2, off);
    }
    if (lane == 0) { sred[wid] = d1; sred2[wid] = d2; }
    __syncthreads();
    if (tid == 0) {
        double t1 = 0.0, t2 = 0.0;
#pragma unroll
        for (int w = 0; w < 8; w++) { t1 += sred[w]; t2 += sred2[w]; }
        atomicAdd(&g_red[2 * ob], t1);
        atomicAdd(&g_red[2 * ob + 1], t2);
    }
}

// ============================================================================
// ctx: CTX[ob][n][i] = sum_j V[kvb(j)][n][jc] * attn[ob][i][j]
// CTA tile 128(n) x 256(i), grid (2, 16, 16), block 256
// ============================================================================
__global__ void __launch_bounds__(256, 1) ctx_mma() {
    extern __shared__ char dsm[];
    uint32_t sb = smem_u32(dsm);

    int ob = blockIdx.z;
    int kvbase = (ob < 8) ? 8 : 0;
    int i0 = blockIdx.x << 8;
    int n0 = blockIdx.y << 7;

    int tid = threadIdx.x;
    int wid = tid >> 5, lane = tid & 31;
    int g = lane >> 2, tg = lane & 3;
    int wm = (wid & 1) * 64, wn = (wid >> 1) * 64;

    uint32_t rowA[4], rowB[4];
    uint32_t lrow = lane & 15, lcol = (lane >> 4) * 16;
#pragma unroll
    for (int mt = 0; mt < 4; mt++) rowA[mt] = (wm + mt * 16 + lrow) * 128 + lcol;
#pragma unroll
    for (int np = 0; np < 4; np++) rowB[np] = (wn + np * 16 + lrow) * 128 + lcol;

    const char* BB = (const char*)g_A + ((size_t)ob * CH + i0) * JD * 2;

    float acc[4][8][4];
#pragma unroll
    for (int a = 0; a < 4; a++)
#pragma unroll
        for (int b = 0; b < 8; b++)
#pragma unroll
            for (int c = 0; c < 4; c++) acc[a][b][c] = 0.f;

    const int NCH = JD / 64;   // 64

    auto load_chunk = [&](int c, int stg) {
        uint32_t s = sb + stg * STAGE_BYTES;
        int j0c = c * 64;
        int kvb = kvbase + (j0c >> 9);
        int jc0 = j0c & 511;
        const char* Ap = (const char*)g_V + (((size_t)kvb * NSEQ + n0) * CH + jc0) * 2;
        ldtile<128>(s,         Ap, CH * 2, tid);
        ldtile<256>(s + 16384, BB + (size_t)j0c * 2, JD * 2, tid);
        cp_commit();
    };

    load_chunk(0, 0);
    load_chunk(1, 1);
    load_chunk(2, 2);
    for (int c = 0; c < NCH; c++) {
        if (c + 2 < NCH) cp_wait_group<2>();
        else if (c + 1 < NCH) cp_wait_group<1>();
        else cp_wait_group<0>();
        __syncthreads();
        if (c + 3 < NCH) load_chunk(c + 3, (c + 3) % NSTG);
        compute_stage(sb + (c % NSTG) * STAGE_BYTES, rowA, rowB, acc);
    }

    const float ds = 1.0f / SCALE_F;   // undo V pre-scale
    float* gout = g_CTX + (size_t)ob * NSEQ * CH;
#pragma unroll
    for (int mt = 0; mt < 4; mt++) {
#pragma unroll
        for (int nt = 0; nt < 8; nt++) {
            int row = n0 + wm + mt * 16 + g;
            int col = i0 + wn + nt * 8 + tg * 2;
            *(float2*)&gout[(size_t)row * CH + col] =
                make_float2(acc[mt][nt][0] * ds, acc[mt][nt][1] * ds);
            *(float2*)&gout[(size_t)(row + 8) * CH + col] =
                make_float2(acc[mt][nt][2] * ds, acc[mt][nt][3] * ds);
        }
    }
}

// ============================================================================
// projection GEMM: C = A[32768,64] @ B[64,512], scaled x256 -> fp16.
// transposed=1 -> out[b][col][n], else out[m][col].
// ============================================================================
__global__ void __launch_bounds__(256) proj_gemm(const float* __restrict__ A,
                                                 const float* __restrict__ Bm,
                                                 __half* __restrict__ OH,
                                                 int transposed) {
    __shared__ __align__(16) float As[16][68];
    __shared__ __align__(16) float Bs[16][64];
    const int K = CDIM, N = CH;
    int bm = blockIdx.y * 64, bn = blockIdx.x * 64;
    int tid = threadIdx.x;
    int tx = tid & 15, ty = tid >> 4;
    int am = tid >> 2, ak = (tid & 3) << 2;
    int br = tid >> 4, bc = (tid & 15) << 2;
    const float* Aptr = A + (size_t)(bm + am) * K + ak;

    float acc[4][4];
#pragma unroll
    for (int i = 0; i < 4; i++)
#pragma unroll
        for (int j = 0; j < 4; j++) acc[i][j] = 0.f;

    for (int k0 = 0; k0 < K; k0 += 16) {
        float4 av = *(const float4*)(Aptr + k0);
        As[ak + 0][am] = av.x; As[ak + 1][am] = av.y;
        As[ak + 2][am] = av.z; As[ak + 3][am] = av.w;
        *(float4*)&Bs[br][bc] = *(const float4*)&Bm[(size_t)(k0 + br) * N + bn + bc];
        __syncthreads();
#pragma unroll
        for (int kk = 0; kk < 16; kk++) {
            float a0 = As[kk][ty * 4 + 0], a1 = As[kk][ty * 4 + 1];
            float a2 = As[kk][ty * 4 + 2], a3 = As[kk][ty * 4 + 3];
            float b0 = Bs[kk][tx * 4 + 0], b1 = Bs[kk][tx * 4 + 1];
            float b2 = Bs[kk][tx * 4 + 2], b3 = Bs[kk][tx * 4 + 3];
            acc[0][0] += a0 * b0; acc[0][1] += a0 * b1; acc[0][2] += a0 * b2; acc[0][3] += a0 * b3;
            acc[1][0] += a1 * b0; acc[1][1] += a1 * b1; acc[1][2] += a1 * b2; acc[1][3] += a1 * b3;
            acc[2][0] += a2 * b0; acc[2][1] += a2 * b1; acc[2][2] += a2 * b2; acc[2][3] += a2 * b3;
            acc[3][0] += a3 * b0; acc[3][1] += a3 * b1; acc[3][2] += a3 * b2; acc[3][3] += a3 * b3;
        }
        __syncthreads();
    }

    if (transposed) {
        int b = bm >> 11;
        int nloc = (bm & 2047) + ty * 4;
#pragma unroll
        for (int j = 0; j < 4; j++) {
            int col = bn + tx * 4 + j;
            union { __half v[4]; uint2 u; } ph;
#pragma unroll
            for (int i = 0; i < 4; i++)
                ph.v[i] = __float2half(acc[i][j] * SCALE_F);
            size_t off = (size_t)b * (CH * NSEQ) + (size_t)col * NSEQ + nloc;
            *(uint2*)&OH[off] = ph.u;
        }
    } else {
#pragma unroll
        for (int i = 0; i < 4; i++) {
            int m = bm + ty * 4 + i;
            union { __half v[4]; uint2 u; } ph;
#pragma unroll
            for (int j = 0; j < 4; j++)
                ph.v[j] = __float2half(acc[i][j] * SCALE_F);
            size_t off = (size_t)m * CH + bn + tx * 4;
            *(uint2*)&OH[off] = ph.u;
        }
    }
}

// ============================================================================
// fp32 NN GEMM (out projection)
// ============================================================================
__global__ void __launch_bounds__(256) gemm_nn(const float* __restrict__ A,
                                               const float* __restrict__ Bm,
                                               float* __restrict__ Cm,
                                               int M, int N, int K) {
    __shared__ __align__(16) float As[16][68];
    __shared__ __align__(16) float Bs[16][64];
    int bm = blockIdx.y * 64, bn = blockIdx.x * 64;
    int tid = threadIdx.x;
    int tx = tid & 15, ty = tid >> 4;
    int am = tid >> 2, ak = (tid & 3) << 2;
    int br = tid >> 4, bc = (tid & 15) << 2;
    const float* Aptr = A + (size_t)(bm + am) * K + ak;

    float acc[4][4];
#pragma unroll
    for (int i = 0; i < 4; i++)
#pragma unroll
        for (int j = 0; j < 4; j++) acc[i][j] = 0.f;

    for (int k0 = 0; k0 < K; k0 += 16) {
        float4 av = *(const float4*)(Aptr + k0);
        As[ak + 0][am] = av.x; As[ak + 1][am] = av.y;
        As[ak + 2][am] = av.z; As[ak + 3][am] = av.w;
        *(float4*)&Bs[br][bc] = *(const float4*)&Bm[(size_t)(k0 + br) * N + bn + bc];
        __syncthreads();
#pragma unroll
        for (int kk = 0; kk < 16; kk++) {
            float a0 = As[kk][ty * 4 + 0], a1 = As[kk][ty * 4 + 1];
            float a2 = As[kk][ty * 4 + 2], a3 = As[kk][ty * 4 + 3];
            float b0 = Bs[kk][tx * 4 + 0], b1 = Bs[kk][tx * 4 + 1];
            float b2 = Bs[kk][tx * 4 + 2], b3 = Bs[kk][tx * 4 + 3];
            acc[0][0] += a0 * b0; acc[0][1] += a0 * b1; acc[0][2] += a0 * b2; acc[0][3] += a0 * b3;
            acc[1][0] += a1 * b0; acc[1][1] += a1 * b1; acc[1][2] += a1 * b2; acc[1][3] += a1 * b3;
            acc[2][0] += a2 * b0; acc[2][1] += a2 * b1; acc[2][2] += a2 * b2; acc[2][3] += a2 * b3;
            acc[3][0] += a3 * b0; acc[3][1] += a3 * b1; acc[3][2] += a3 * b2; acc[3][3] += a3 * b3;
        }
        __syncthreads();
    }
#pragma unroll
    for (int i = 0; i < 4; i++) {
        float4 v = make_float4(acc[i][0], acc[i][1], acc[i][2], acc[i][3]);
        *(float4*)&Cm[(size_t)(bm + ty * 4 + i) * N + bn + tx * 4] = v;
    }
}

// ============================================================================
// instance-norm finalize + softmax
// ============================================================================
__global__ void zero_red_k() {
    int t = threadIdx.x;
    if (t < BTOT) { g_red[2 * t] = 0.0; g_red[2 * t + 1] = 0.0; }
}

__global__ void finalize_k() {
    int t = threadIdx.x;
    if (t < BTOT) {
        const double SC = 65536.0;   // scores are scaled by 2^16
        double n = (double)CH * (double)JD;
        double mean = g_red[2 * t] / (n * SC);
        double var  = g_red[2 * t + 1] / (n * SC * SC) - mean * mean;
        g_rstd[t] = rsqrtf((float)var + EPS_F) / (float)SC;
    }
}

__global__ void __launch_bounds__(256) softmax_k() {
    int row = blockIdx.x;
    int b = row >> 9;
    float rstd = g_rstd[b];          // already includes 1/2^16
    const float* p = g_S + (size_t)row * JD;
    __half* ah = g_A + (size_t)row * JD;
    int t = threadIdx.x;

    float x[16];
    float mx = -1e30f;
#pragma unroll
    for (int u = 0; u < 16; u++) {
        x[u] = p[u * 256 + t] * rstd;
        mx = fmaxf(mx, x[u]);
    }
    __shared__ float red[8];
    for (int off = 16; off > 0; off >>= 1)
        mx = fmaxf(mx, __shfl_xor_sync(0xffffffffu, mx, off));
    int lane = t & 31, wid = t >> 5;
    if (lane == 0) red[wid] = mx;
    __syncthreads();
    float gm = red[0];
#pragma unroll
    for (int w = 1; w < 8; w++) gm = fmaxf(gm, red[w]);
    __syncthreads();

    float sum = 0.f;
#pragma unroll
    for (int u = 0; u < 16; u++) {
        x[u] = __expf(x[u] - gm);
        sum += x[u];
    }
    for (int off = 16; off > 0; off >>= 1)
        sum += __shfl_xor_sync(0xffffffffu, sum, off);
    if (lane == 0) red[wid] = sum;
    __syncthreads();
    float tot = 0.f;
#pragma unroll
    for (int w = 0; w < 8; w++) tot += red[w];
    float inv = 1.0f / tot;
#pragma unroll
    for (int u = 0; u < 16; u++)
        ah[u * 256 + t] = __float2half(x[u] * inv);
}

// ============================================================================
// launch
// ============================================================================
extern "C" void kernel_launch(void* const* d_in, const int* in_sizes, int n_in,
                              void* d_out, int out_size) {
    const float* emb = (const float*)d_in[0];
    const float* Wq  = (const float*)d_in[1];
    const float* Wk  = (const float*)d_in[2];
    const float* Wv  = (const float*)d_in[3];
    const float* Wo  = (const float*)d_in[4];
    float* outp = (float*)d_out;

    void *qt, *kt, *vv, *cx;
    cudaGetSymbolAddress(&qt, g_Qt);
    cudaGetSymbolAddress(&kt, g_Kt);
    cudaGetSymbolAddress(&vv, g_V);
    cudaGetSymbolAddress(&cx, g_CTX);

    cudaFuncSetAttribute(scores_mma, cudaFuncAttributeMaxDynamicSharedMemorySize, SMEM_DYN);
    cudaFuncSetAttribute(ctx_mma, cudaFuncAttributeMaxDynamicSharedMemorySize, SMEM_DYN);

    dim3 gproj(CH / 64, ROWS_TOT / 64);
    proj_gemm<<<gproj, 256>>>(emb, Wq, (__half*)qt, 1);
    proj_gemm<<<gproj, 256>>>(emb, Wk, (__half*)kt, 1);
    proj_gemm<<<gproj, 256>>>(emb, Wv, (__half*)vv, 0);

    zero_red_k<<<1, 32>>>();
    scores_mma<<<dim3(JD / 256, CH / 128, BTOT), 256, SMEM_DYN>>>();
    finalize_k<<<1, 32>>>();
    softmax_k<<<BTOT * CH, 256>>>();

    ctx_mma<<<dim3(CH / 256, NSEQ / 128, BTOT), 256, SMEM_DYN>>>();

    gemm_nn<<<dim3(CDIM / 64, ROWS_TOT / 64), 256>>>((const float*)cx, Wo, outp,
                                                     ROWS_TOT, CDIM, CH);
}

// round 8
// speedup vs baseline: 1.6805x; 1.0436x over previous
#include <cuda_runtime.h>
#include <cuda_fp16.h>
#include <cstdint>
#include <cstddef>

#define NSEQ  2048
#define CDIM  64
#define CH    512
#define JD    4096
#define BTOT  16
#define ROWS_TOT (BTOT * NSEQ)
#define EPS_F 1e-5f
#define SCALE_F 256.0f          // operand pre-scale (2^8)

// stage (k64): A 128x64 fp16 = 16KB, B 256x64 fp16 = 32KB
#define STAGE_BYTES 49152
#define NSTG 4
#define SMEM_DYN (NSTG * STAGE_BYTES)

// ---------------- scratch ----------------
__device__ __half g_Qt[(size_t)BTOT * CH * NSEQ];    // [b][i][n], x256
__device__ __half g_Kt[(size_t)BTOT * CH * NSEQ];    // [b][j][n], x256
__device__ __half g_V [(size_t)BTOT * NSEQ * CH];    // [b][n][c], x256
__device__ float  g_S [(size_t)BTOT * CH * JD];      // scores, x2^16
__device__ __half g_A [(size_t)BTOT * CH * JD];      // attn fp16 [b][i][j]
__device__ float  g_CTX[(size_t)BTOT * NSEQ * CH];   // true scale
__device__ double g_red[BTOT * 2];

// ---------------- helpers ----------------
__device__ __forceinline__ uint32_t smem_u32(const void* p) {
    uint32_t a;
    asm("{ .reg .u64 t; cvta.to.shared.u64 t, %1; cvt.u32.u64 %0, t; }" : "=r"(a) : "l"(p));
    return a;
}
__device__ __forceinline__ void cp_async16(uint32_t s, const void* g) {
    asm volatile("cp.async.cg.shared.global [%0], [%1], 16;" :: "r"(s), "l"(g) : "memory");
}
__device__ __forceinline__ void cp_commit() {
    asm volatile("cp.async.commit_group;" ::: "memory");
}
template <int N>
__device__ __forceinline__ void cp_wait_group() {
    asm volatile("cp.async.wait_group %0;" :: "n"(N) : "memory");
}
// SW128 swizzle for 128-byte rows
__device__ __forceinline__ uint32_t swz(uint32_t off) {
    return off ^ ((off >> 3) & 0x70);
}
__device__ __forceinline__ void mma16816h(float* c, const uint32_t a[4],
                                          uint32_t b0, uint32_t b1) {
    asm volatile(
        "mma.sync.aligned.m16n8k16.row.col.f32.f16.f16.f32 "
        "{%0,%1,%2,%3}, {%4,%5,%6,%7}, {%8,%9}, {%0,%1,%2,%3};"
        : "+f"(c[0]), "+f"(c[1]), "+f"(c[2]), "+f"(c[3])
        : "r"(a[0]), "r"(a[1]), "r"(a[2]), "r"(a[3]), "r"(b0), "r"(b1));
}
__device__ __forceinline__ void ldsm4(uint32_t r[4], uint32_t addr) {
    asm volatile("ldmatrix.sync.aligned.m8n8.x4.shared.b16 {%0,%1,%2,%3}, [%4];"
                 : "=r"(r[0]), "=r"(r[1]), "=r"(r[2]), "=r"(r[3]) : "r"(addr));
}

// load ROWS x 64 fp16 tile (128B rows) into SW128-swizzled smem
template <int ROWS>
__device__ __forceinline__ void ldtile(uint32_t sdst, const char* g, size_t stride, int tid) {
#pragma unroll
    for (int t = 0; t < ROWS / 32; t++) {
        int op = tid + t * 256;
        int row = op >> 3, c = op & 7;
        uint32_t off = row * 128 + c * 16;
        cp_async16(sdst + swz(off), g + (size_t)row * stride + c * 16);
    }
}

// ============================================================================
// single-term fp16 compute for one k64 stage; warp tile 64x64 (4 mt x 8 nt)
// ============================================================================
__device__ __forceinline__ void compute_stage(uint32_t sb, const uint32_t rowA[4],
                                              const uint32_t rowB[4],
                                              float acc[4][8][4]) {
    uint32_t sA = sb, sB = sb + 16384;
#pragma unroll
    for (int kk = 0; kk < 4; kk++) {
        uint32_t kb = kk * 32;
        uint32_t ah[4][4], bf[4][4];
#pragma unroll
        for (int mt = 0; mt < 4; mt++)
            ldsm4(ah[mt], sA + swz(rowA[mt] + kb));
#pragma unroll
        for (int np = 0; np < 4; np++)
            ldsm4(bf[np], sB + swz(rowB[np] + kb));
#pragma unroll
        for (int np = 0; np < 4; np++) {
#pragma unroll
            for (int h = 0; h < 2; h++) {
                uint32_t b0 = bf[np][h], b1 = bf[np][2 + h];
                int nt = np * 2 + h;
#pragma unroll
                for (int mt = 0; mt < 4; mt++)
                    mma16816h(acc[mt][nt], ah[mt], b0, b1);
            }
        }
    }
}

// ============================================================================
// scores: S[ob][i][j] = sum_n Qt[ob][i][n] * Kt[kvb][jc][n]   (x 2^16)
// CTA tile 128(i) x 256(j), grid (16, 4, 16), block 256
// ============================================================================
__global__ void __launch_bounds__(256, 1) scores_mma() {
    extern __shared__ char dsm[];
    uint32_t sb = smem_u32(dsm);
    __shared__ double sred[8], sred2[8];

    int ob = blockIdx.z;
    int kvbase = (ob < 8) ? 8 : 0;
    int i0 = blockIdx.y << 7;
    int j0 = blockIdx.x << 8;
    int kvb = kvbase + (j0 >> 9);
    int jc0 = j0 & 511;

    int tid = threadIdx.x;
    int wid = tid >> 5, lane = tid & 31;
    int g = lane >> 2, tg = lane & 3;
    int wm = (wid & 1) * 64, wn = (wid >> 1) * 64;

    uint32_t rowA[4], rowB[4];
    uint32_t lrow = lane & 15, lcol = (lane >> 4) * 16;
#pragma unroll
    for (int mt = 0; mt < 4; mt++) rowA[mt] = (wm + mt * 16 + lrow) * 128 + lcol;
#pragma unroll
    for (int np = 0; np < 4; np++) rowB[np] = (wn + np * 16 + lrow) * 128 + lcol;

    const char* AB = (const char*)g_Qt + ((size_t)ob * CH + i0) * NSEQ * 2;
    const char* BB = (const char*)g_Kt + ((size_t)kvb * CH + jc0) * NSEQ * 2;
    const size_t st = NSEQ * 2;

    float acc[4][8][4];
#pragma unroll
    for (int a = 0; a < 4; a++)
#pragma unroll
        for (int b = 0; b < 8; b++)
#pragma unroll
            for (int c = 0; c < 4; c++) acc[a][b][c] = 0.f;

    const int NCH = NSEQ / 64;   // 32

    auto load_chunk = [&](int c, int stg) {
        uint32_t s = sb + stg * STAGE_BYTES;
        size_t ko = (size_t)c * 128;
        ldtile<128>(s,         AB + ko, st, tid);
        ldtile<256>(s + 16384, BB + ko, st, tid);
        cp_commit();
    };

    load_chunk(0, 0);
    load_chunk(1, 1);
    load_chunk(2, 2);
    for (int c = 0; c < NCH; c++) {
        if (c + 2 < NCH) cp_wait_group<2>();
        else if (c + 1 < NCH) cp_wait_group<1>();
        else cp_wait_group<0>();
        __syncthreads();
        if (c + 3 < NCH) load_chunk(c + 3, (c + 3) % NSTG);
        compute_stage(sb + (c % NSTG) * STAGE_BYTES, rowA, rowB, acc);
    }

    // write scores + fused sum/sumsq
    float* gout = g_S + (size_t)ob * CH * JD;
    float s1 = 0.f, s2 = 0.f;
#pragma unroll
    for (int mt = 0; mt < 4; mt++) {
#pragma unroll
        for (int nt = 0; nt < 8; nt++) {
            int row = i0 + wm + mt * 16 + g;
            int col = j0 + wn + nt * 8 + tg * 2;
            float v0 = acc[mt][nt][0], v1 = acc[mt][nt][1];
            float v2 = acc[mt][nt][2], v3 = acc[mt][nt][3];
            *(float2*)&gout[(size_t)row * JD + col] = make_float2(v0, v1);
            *(float2*)&gout[(size_t)(row + 8) * JD + col] = make_float2(v2, v3);
            s1 += v0 + v1 + v2 + v3;
            s2 += v0 * v0 + v1 * v1 + v2 * v2 + v3 * v3;
        }
    }
    double d1 = (double)s1, d2 = (double)s2;
    for (int off = 16; off > 0; off >>= 1) {
        d1 += __shfl_down_sync(0xffffffffu, d1, off);
        d2 += __shfl_down_sync(0xffffffffu, d2, off);
    }
    if (lane == 0) { sred[wid] = d1; sred2[wid] = d2; }
    __syncthreads();
    if (tid == 0) {
        double t1 = 0.0, t2 = 0.0;
#pragma unroll
        for (int w = 0; w < 8; w++) { t1 += sred[w]; t2 += sred2[w]; }
        atomicAdd(&g_red[2 * ob], t1);
        atomicAdd(&g_red[2 * ob + 1], t2);
    }
}

// ============================================================================
// ctx: CTX[ob][n][i] = sum_j V[kvb(j)][n][jc] * attn[ob][i][j]
// CTA tile 128(n) x 256(i), grid (2, 16, 16), block 256
// ============================================================================
__global__ void __launch_bounds__(256, 1) ctx_mma() {
    extern __shared__ char dsm[];
    uint32_t sb = smem_u32(dsm);

    int ob = blockIdx.z;
    int kvbase = (ob < 8) ? 8 : 0;
    int i0 = blockIdx.x << 8;
    int n0 = blockIdx.y << 7;

    int tid = threadIdx.x;
    int wid = tid >> 5, lane = tid & 31;
    int g = lane >> 2, tg = lane & 3;
    int wm = (wid & 1) * 64, wn = (wid >> 1) * 64;

    uint32_t rowA[4], rowB[4];
    uint32_t lrow = lane & 15, lcol = (lane >> 4) * 16;
#pragma unroll
    for (int mt = 0; mt < 4; mt++) rowA[mt] = (wm + mt * 16 + lrow) * 128 + lcol;
#pragma unroll
    for (int np = 0; np < 4; np++) rowB[np] = (wn + np * 16 + lrow) * 128 + lcol;

    const char* BB = (const char*)g_A + ((size_t)ob * CH + i0) * JD * 2;

    float acc[4][8][4];
#pragma unroll
    for (int a = 0; a < 4; a++)
#pragma unroll
        for (int b = 0; b < 8; b++)
#pragma unroll
            for (int c = 0; c < 4; c++) acc[a][b][c] = 0.f;

    const int NCH = JD / 64;   // 64

    auto load_chunk = [&](int c, int stg) {
        uint32_t s = sb + stg * STAGE_BYTES;
        int j0c = c * 64;
        int kvb = kvbase + (j0c >> 9);
        int jc0 = j0c & 511;
        const char* Ap = (const char*)g_V + (((size_t)kvb * NSEQ + n0) * CH + jc0) * 2;
        ldtile<128>(s,         Ap, CH * 2, tid);
        ldtile<256>(s + 16384, BB + (size_t)j0c * 2, JD * 2, tid);
        cp_commit();
    };

    load_chunk(0, 0);
    load_chunk(1, 1);
    load_chunk(2, 2);
    for (int c = 0; c < NCH; c++) {
        if (c + 2 < NCH) cp_wait_group<2>();
        else if (c + 1 < NCH) cp_wait_group<1>();
        else cp_wait_group<0>();
        __syncthreads();
        if (c + 3 < NCH) load_chunk(c + 3, (c + 3) % NSTG);
        compute_stage(sb + (c % NSTG) * STAGE_BYTES, rowA, rowB, acc);
    }

    const float ds = 1.0f / SCALE_F;   // undo V pre-scale
    float* gout = g_CTX + (size_t)ob * NSEQ * CH;
#pragma unroll
    for (int mt = 0; mt < 4; mt++) {
#pragma unroll
        for (int nt = 0; nt < 8; nt++) {
            int row = n0 + wm + mt * 16 + g;
            int col = i0 + wn + nt * 8 + tg * 2;
            *(float2*)&gout[(size_t)row * CH + col] =
                make_float2(acc[mt][nt][0] * ds, acc[mt][nt][1] * ds);
            *(float2*)&gout[(size_t)(row + 8) * CH + col] =
                make_float2(acc[mt][nt][2] * ds, acc[mt][nt][3] * ds);
        }
    }
}

// ============================================================================
// fused QKV projection: Qt/Kt (transposed) + V (row) from one emb tile read.
// grid (CH/64=8, ROWS_TOT/64=512), 256 threads. Also zeroes g_red.
// ============================================================================
__global__ void __launch_bounds__(256) qkv_gemm(const float* __restrict__ A,
                                                const float* __restrict__ BmQ,
                                                const float* __restrict__ BmK,
                                                const float* __restrict__ BmV,
                                                __half* __restrict__ Qt,
                                                __half* __restrict__ Kt,
                                                __half* __restrict__ Vv) {
    __shared__ __align__(16) float As[16][68];
    __shared__ __align__(16) float BsQ[16][64], BsK[16][64], BsV[16][64];
    const int K = CDIM, N = CH;
    int bm = blockIdx.y * 64, bn = blockIdx.x * 64;
    int tid = threadIdx.x;

    if (blockIdx.x == 0 && blockIdx.y == 0 && tid < BTOT * 2)
        g_red[tid] = 0.0;

    int tx = tid & 15, ty = tid >> 4;
    int am = tid >> 2, ak = (tid & 3) << 2;
    int br = tid >> 4, bc = (tid & 15) << 2;
    const float* Aptr = A + (size_t)(bm + am) * K + ak;

    float aq[4][4], akk[4][4], av_[4][4];
#pragma unroll
    for (int i = 0; i < 4; i++)
#pragma unroll
        for (int j = 0; j < 4; j++) { aq[i][j] = 0.f; akk[i][j] = 0.f; av_[i][j] = 0.f; }

    for (int k0 = 0; k0 < K; k0 += 16) {
        float4 avv = *(const float4*)(Aptr + k0);
        As[ak + 0][am] = avv.x; As[ak + 1][am] = avv.y;
        As[ak + 2][am] = avv.z; As[ak + 3][am] = avv.w;
        size_t boff = (size_t)(k0 + br) * N + bn + bc;
        *(float4*)&BsQ[br][bc] = *(const float4*)&BmQ[boff];
        *(float4*)&BsK[br][bc] = *(const float4*)&BmK[boff];
        *(float4*)&BsV[br][bc] = *(const float4*)&BmV[boff];
        __syncthreads();
#pragma unroll
        for (int kk = 0; kk < 16; kk++) {
            float a0 = As[kk][ty * 4 + 0], a1 = As[kk][ty * 4 + 1];
            float a2 = As[kk][ty * 4 + 2], a3 = As[kk][ty * 4 + 3];
#pragma unroll
            for (int j = 0; j < 4; j++) {
                float bq = BsQ[kk][tx * 4 + j];
                float bk = BsK[kk][tx * 4 + j];
                float bv = BsV[kk][tx * 4 + j];
                aq[0][j] += a0 * bq; aq[1][j] += a1 * bq; aq[2][j] += a2 * bq; aq[3][j] += a3 * bq;
                akk[0][j] += a0 * bk; akk[1][j] += a1 * bk; akk[2][j] += a2 * bk; akk[3][j] += a3 * bk;
                av_[0][j] += a0 * bv; av_[1][j] += a1 * bv; av_[2][j] += a2 * bv; av_[3][j] += a3 * bv;
            }
        }
        __syncthreads();
    }

    // Qt / Kt transposed epilogue: out[b][col][n]
    {
        int b = bm >> 11;
        int nloc = (bm & 2047) + ty * 4;
#pragma unroll
        for (int j = 0; j < 4; j++) {
            int col = bn + tx * 4 + j;
            union { __half v[4]; uint2 u; } pq, pk;
#pragma unroll
            for (int i = 0; i < 4; i++) {
                pq.v[i] = __float2half(aq[i][j] * SCALE_F);
                pk.v[i] = __float2half(akk[i][j] * SCALE_F);
            }
            size_t off = (size_t)b * (CH * NSEQ) + (size_t)col * NSEQ + nloc;
            *(uint2*)&Qt[off] = pq.u;
            *(uint2*)&Kt[off] = pk.u;
        }
    }
    // V row-major epilogue
#pragma unroll
    for (int i = 0; i < 4; i++) {
        int m = bm + ty * 4 + i;
        union { __half v[4]; uint2 u; } pv;
#pragma unroll
        for (int j = 0; j < 4; j++)
            pv.v[j] = __float2half(av_[i][j] * SCALE_F);
        *(uint2*)&Vv[(size_t)m * CH + bn + tx * 4] = pv.u;
    }
}

// ============================================================================
// out projection fp32: C[M,64] = CTX[M,512] @ Wo[512,64]; 128x64 tile.
// grid (M/128=256), 256 threads, 8x4 per thread.
// ============================================================================
__global__ void __launch_bounds__(256) gemm_out(const float* __restrict__ A,
                                                const float* __restrict__ Bm,
                                                float* __restrict__ Cm) {
    __shared__ __align__(16) float As[16][132];
    __shared__ __align__(16) float Bs[16][64];
    const int K = CH, N = CDIM;
    int bm = blockIdx.x * 128;
    int tid = threadIdx.x;
    int tx = tid & 15, ty = tid >> 4;
    int am = tid >> 2, ak = (tid & 3) << 2;
    int br = tid >> 4, bc = (tid & 15) << 2;

    float acc[8][4];
#pragma unroll
    for (int i = 0; i < 8; i++)
#pragma unroll
        for (int j = 0; j < 4; j++) acc[i][j] = 0.f;

    for (int k0 = 0; k0 < K; k0 += 16) {
        float4 a0v = *(const float4*)&A[(size_t)(bm + am) * K + k0 + ak];
        float4 a1v = *(const float4*)&A[(size_t)(bm + am + 64) * K + k0 + ak];
        As[ak + 0][am] = a0v.x; As[ak + 1][am] = a0v.y;
        As[ak + 2][am] = a0v.z; As[ak + 3][am] = a0v.w;
        As[ak + 0][am + 64] = a1v.x; As[ak + 1][am + 64] = a1v.y;
        As[ak + 2][am + 64] = a1v.z; As[ak + 3][am + 64] = a1v.w;
        *(float4*)&Bs[br][bc] = *(const float4*)&Bm[(size_t)(k0 + br) * N + bc];
        __syncthreads();
#pragma unroll
        for (int kk = 0; kk < 16; kk++) {
            float a[8], b[4];
            *(float4*)&a[0] = *(float4*)&As[kk][ty * 8];
            *(float4*)&a[4] = *(float4*)&As[kk][ty * 8 + 4];
            *(float4*)&b[0] = *(float4*)&Bs[kk][tx * 4];
#pragma unroll
            for (int i = 0; i < 8; i++)
#pragma unroll
                for (int j = 0; j < 4; j++) acc[i][j] += a[i] * b[j];
        }
        __syncthreads();
    }
#pragma unroll
    for (int i = 0; i < 8; i++) {
        float4 v = make_float4(acc[i][0], acc[i][1], acc[i][2], acc[i][3]);
        *(float4*)&Cm[(size_t)(bm + ty * 8 + i) * N + tx * 4] = v;
    }
}

// ============================================================================
// softmax (fused rstd finalize): scale + softmax over j, write attn fp16.
// grid (8192), 256 threads, float4 IO.
// ============================================================================
__global__ void __launch_bounds__(256) softmax_k() {
    int row = blockIdx.x;
    int b = row >> 9;
    __shared__ float srstd;
    __shared__ float red[8];
    int t = threadIdx.x;

    if (t == 0) {
        const double SC = 65536.0;   // scores are scaled by 2^16
        double n = (double)CH * (double)JD;
        double mean = g_red[2 * b] / (n * SC);
        double var  = g_red[2 * b + 1] / (n * SC * SC) - mean * mean;
        srstd = rsqrtf((float)var + EPS_F) / (float)SC;
    }

    const float* p = g_S + (size_t)row * JD;
    float4 xv[4];
#pragma unroll
    for (int u = 0; u < 4; u++)
        xv[u] = *(const float4*)&p[u * 1024 + t * 4];
    __syncthreads();
    float rstd = srstd;

    float* x = (float*)xv;
    float mx = -1e30f;
#pragma unroll
    for (int u = 0; u < 16; u++) {
        x[u] *= rstd;
        mx = fmaxf(mx, x[u]);
    }
    for (int off = 16; off > 0; off >>= 1)
        mx = fmaxf(mx, __shfl_xor_sync(0xffffffffu, mx, off));
    int lane = t & 31, wid = t >> 5;
    if (lane == 0) red[wid] = mx;
    __syncthreads();
    float gm = red[0];
#pragma unroll
    for (int w = 1; w < 8; w++) gm = fmaxf(gm, red[w]);
    __syncthreads();

    float sum = 0.f;
#pragma unroll
    for (int u = 0; u < 16; u++) {
        x[u] = __expf(x[u] - gm);
        sum += x[u];
    }
    for (int off = 16; off > 0; off >>= 1)
        sum += __shfl_xor_sync(0xffffffffu, sum, off);
    if (lane == 0) red[wid] = sum;
    __syncthreads();
    float tot = 0.f;
#pragma unroll
    for (int w = 0; w < 8; w++) tot += red[w];
    float inv = 1.0f / tot;

    __half* ah = g_A + (size_t)row * JD;
#pragma unroll
    for (int u = 0; u < 4; u++) {
        union { __half v[4]; uint2 q; } pk;
#pragma unroll
        for (int e = 0; e < 4; e++)
            pk.v[e] = __float2half(x[u * 4 + e] * inv);
        *(uint2*)&ah[u * 1024 + t * 4] = pk.q;
    }
}

// ============================================================================
// launch
// ============================================================================
extern "C" void kernel_launch(void* const* d_in, const int* in_sizes, int n_in,
                              void* d_out, int out_size) {
    const float* emb = (const float*)d_in[0];
    const float* Wq  = (const float*)d_in[1];
    const float* Wk  = (const float*)d_in[2];
    const float* Wv  = (const float*)d_in[3];
    const float* Wo  = (const float*)d_in[4];
    float* outp = (float*)d_out;

    void *qt, *kt, *vv, *cx;
    cudaGetSymbolAddress(&qt, g_Qt);
    cudaGetSymbolAddress(&kt, g_Kt);
    cudaGetSymbolAddress(&vv, g_V);
    cudaGetSymbolAddress(&cx, g_CTX);

    cudaFuncSetAttribute(scores_mma, cudaFuncAttributeMaxDynamicSharedMemorySize, SMEM_DYN);
    cudaFuncSetAttribute(ctx_mma, cudaFuncAttributeMaxDynamicSharedMemorySize, SMEM_DYN);

    qkv_gemm<<<dim3(CH / 64, ROWS_TOT / 64), 256>>>(emb, Wq, Wk, Wv,
                                                    (__half*)qt, (__half*)kt, (__half*)vv);

    scores_mma<<<dim3(JD / 256, CH / 128, BTOT), 256, SMEM_DYN>>>();

    softmax_k<<<BTOT * CH, 256>>>();

    ctx_mma<<<dim3(CH / 256, NSEQ / 128, BTOT), 256, SMEM_DYN>>>();

    gemm_out<<<ROWS_TOT / 128, 256>>>((const float*)cx, Wo, outp);
}

// round 9
// speedup vs baseline: 1.8355x; 1.0923x over previous
#include <cuda_runtime.h>
#include <cuda_fp16.h>
#include <cstdint>
#include <cstddef>

#define NSEQ  2048
#define CDIM  64
#define CH    512
#define JD    4096
#define BTOT  16
#define ROWS_TOT (BTOT * NSEQ)
#define EPS_F 1e-5f
#define SCALE_F 256.0f          // operand pre-scale (2^8)

// stage (k64): A 128x64 fp16 = 16KB, B 128x64 fp16 = 16KB
#define STAGE_BYTES 32768
#define NSTG 3
#define SMEM_DYN (NSTG * STAGE_BYTES)

// ---------------- scratch ----------------
__device__ __half g_Qt[(size_t)BTOT * CH * NSEQ];    // [b][i][n], x256
__device__ __half g_Kt[(size_t)BTOT * CH * NSEQ];    // [b][j][n], x256
__device__ __half g_V [(size_t)BTOT * NSEQ * CH];    // [b][n][c], x256
__device__ float  g_S [(size_t)BTOT * CH * JD];      // scores, x2^16
__device__ __half g_A [(size_t)BTOT * CH * JD];      // attn fp16 [b][i][j]
__device__ float  g_CTX[(size_t)BTOT * NSEQ * CH];   // true scale
__device__ double g_red[BTOT * 2];

// ---------------- helpers ----------------
__device__ __forceinline__ uint32_t smem_u32(const void* p) {
    uint32_t a;
    asm("{ .reg .u64 t; cvta.to.shared.u64 t, %1; cvt.u32.u64 %0, t; }" : "=r"(a) : "l"(p));
    return a;
}
__device__ __forceinline__ void cp_async16(uint32_t s, const void* g) {
    asm volatile("cp.async.cg.shared.global [%0], [%1], 16;" :: "r"(s), "l"(g) : "memory");
}
__device__ __forceinline__ void cp_commit() {
    asm volatile("cp.async.commit_group;" ::: "memory");
}
template <int N>
__device__ __forceinline__ void cp_wait_group() {
    asm volatile("cp.async.wait_group %0;" :: "n"(N) : "memory");
}
// SW128 swizzle for 128-byte rows
__device__ __forceinline__ uint32_t swz(uint32_t off) {
    return off ^ ((off >> 3) & 0x70);
}
__device__ __forceinline__ void mma16816h(float* c, const uint32_t a[4],
                                          uint32_t b0, uint32_t b1) {
    asm volatile(
        "mma.sync.aligned.m16n8k16.row.col.f32.f16.f16.f32 "
        "{%0,%1,%2,%3}, {%4,%5,%6,%7}, {%8,%9}, {%0,%1,%2,%3};"
        : "+f"(c[0]), "+f"(c[1]), "+f"(c[2]), "+f"(c[3])
        : "r"(a[0]), "r"(a[1]), "r"(a[2]), "r"(a[3]), "r"(b0), "r"(b1));
}
__device__ __forceinline__ void ldsm4(uint32_t r[4], uint32_t addr) {
    asm volatile("ldmatrix.sync.aligned.m8n8.x4.shared.b16 {%0,%1,%2,%3}, [%4];"
                 : "=r"(r[0]), "=r"(r[1]), "=r"(r[2]), "=r"(r[3]) : "r"(addr));
}

// load 128 x 64 fp16 tile (128B rows) into SW128-swizzled smem (256 threads)
__device__ __forceinline__ void ldtile(uint32_t sdst, const char* g, size_t stride, int tid) {
#pragma unroll
    for (int t = 0; t < 4; t++) {
        int op = tid + t * 256;
        int row = op >> 3, c = op & 7;
        uint32_t off = row * 128 + c * 16;
        cp_async16(sdst + swz(off), g + (size_t)row * stride + c * 16);
    }
}

// ============================================================================
// single-term fp16 compute for one k64 stage; warp tile 64x32 (4 mt x 4 nt)
// baseA/baseB are PRE-SWIZZLED smem addresses; k-offset applied via XOR
// (valid: row bits 5-6 are zero, kb in {0,32,64,96}).
// ============================================================================
__device__ __forceinline__ void compute_stage(uint32_t sA, uint32_t sB,
                                              const uint32_t baseA[4],
                                              const uint32_t baseB[2],
                                              float acc[4][4][4]) {
#pragma unroll
    for (int kk = 0; kk < 4; kk++) {
        uint32_t kb = kk * 32;
        uint32_t ah[4][4], bf[2][4];
#pragma unroll
        for (int mt = 0; mt < 4; mt++)
            ldsm4(ah[mt], sA + (baseA[mt] ^ kb));
#pragma unroll
        for (int np = 0; np < 2; np++)
            ldsm4(bf[np], sB + (baseB[np] ^ kb));
#pragma unroll
        for (int np = 0; np < 2; np++) {
#pragma unroll
            for (int h = 0; h < 2; h++) {
                uint32_t b0 = bf[np][h], b1 = bf[np][2 + h];
                int nt = np * 2 + h;
#pragma unroll
                for (int mt = 0; mt < 4; mt++)
                    mma16816h(acc[mt][nt], ah[mt], b0, b1);
            }
        }
    }
}

// ============================================================================
// scores: S[ob][i][j] = sum_n Qt[ob][i][n] * Kt[kvb][jc][n]   (x 2^16)
// CTA tile 128(i) x 128(j), grid (32, 4, 16), block 256, 2 CTAs/SM
// ============================================================================
__global__ void __launch_bounds__(256, 2) scores_mma() {
    extern __shared__ char dsm[];
    uint32_t sb = smem_u32(dsm);
    __shared__ double sred[8], sred2[8];

    int ob = blockIdx.z;
    int kvbase = (ob < 8) ? 8 : 0;
    int i0 = blockIdx.y << 7;
    int j0 = blockIdx.x << 7;
    int kvb = kvbase + (j0 >> 9);
    int jc0 = j0 & 511;

    int tid = threadIdx.x;
    int wid = tid >> 5, lane = tid & 31;
    int g = lane >> 2, tg = lane & 3;
    int wm = (wid & 1) * 64, wn = (wid >> 1) * 32;

    uint32_t baseA[4], baseB[2];
    uint32_t lrow = lane & 15, lcol = (lane >> 4) * 16;
#pragma unroll
    for (int mt = 0; mt < 4; mt++) baseA[mt] = swz((wm + mt * 16 + lrow) * 128 + lcol);
#pragma unroll
    for (int np = 0; np < 2; np++) baseB[np] = swz((wn + np * 16 + lrow) * 128 + lcol);

    const char* AB = (const char*)g_Qt + ((size_t)ob * CH + i0) * NSEQ * 2;
    const char* BB = (const char*)g_Kt + ((size_t)kvb * CH + jc0) * NSEQ * 2;
    const size_t st = NSEQ * 2;

    float acc[4][4][4];
#pragma unroll
    for (int a = 0; a < 4; a++)
#pragma unroll
        for (int b = 0; b < 4; b++)
#pragma unroll
            for (int c = 0; c < 4; c++) acc[a][b][c] = 0.f;

    const int NCH = NSEQ / 64;   // 32

    auto load_chunk = [&](int c, int stg) {
        uint32_t s = sb + stg * STAGE_BYTES;
        size_t ko = (size_t)c * 128;
        ldtile(s,         AB + ko, st, tid);
        ldtile(s + 16384, BB + ko, st, tid);
        cp_commit();
    };

    load_chunk(0, 0);
    load_chunk(1, 1);
    for (int c = 0; c < NCH; c++) {
        if (c + 1 < NCH) cp_wait_group<1>(); else cp_wait_group<0>();
        __syncthreads();
        if (c + 2 < NCH) load_chunk(c + 2, (c + 2) % NSTG);
        uint32_t s = sb + (c % NSTG) * STAGE_BYTES;
        compute_stage(s, s + 16384, baseA, baseB, acc);
    }

    // write scores + fused sum/sumsq
    float* gout = g_S + (size_t)ob * CH * JD;
    float s1 = 0.f, s2 = 0.f;
#pragma unroll
    for (int mt = 0; mt < 4; mt++) {
#pragma unroll
        for (int nt = 0; nt < 4; nt++) {
            int row = i0 + wm + mt * 16 + g;
            int col = j0 + wn + nt * 8 + tg * 2;
            float v0 = acc[mt][nt][0], v1 = acc[mt][nt][1];
            float v2 = acc[mt][nt][2], v3 = acc[mt][nt][3];
            *(float2*)&gout[(size_t)row * JD + col] = make_float2(v0, v1);
            *(float2*)&gout[(size_t)(row + 8) * JD + col] = make_float2(v2, v3);
            s1 += v0 + v1 + v2 + v3;
            s2 += v0 * v0 + v1 * v1 + v2 * v2 + v3 * v3;
        }
    }
    double d1 = (double)s1, d2 = (double)s2;
    for (int off = 16; off > 0; off >>= 1) {
        d1 += __shfl_down_sync(0xffffffffu, d1, off);
        d2 += __shfl_down_sync(0xffffffffu, d2, off);
    }
    if (lane == 0) { sred[wid] = d1; sred2[wid] = d2; }
    __syncthreads();
    if (tid == 0) {
        double t1 = 0.0, t2 = 0.0;
#pragma unroll
        for (int w = 0; w < 8; w++) { t1 += sred[w]; t2 += sred2[w]; }
        atomicAdd(&g_red[2 * ob], t1);
        atomicAdd(&g_red[2 * ob + 1], t2);
    }
}

// ============================================================================
// ctx: CTX[ob][n][i] = sum_j V[kvb(j)][n][jc] * attn[ob][i][j]
// CTA tile 128(n) x 128(i), grid (4, 16, 16), block 256, 2 CTAs/SM
// ============================================================================
__global__ void __launch_bounds__(256, 2) ctx_mma() {
    extern __shared__ char dsm[];
    uint32_t sb = smem_u32(dsm);

    int ob = blockIdx.z;
    int kvbase = (ob < 8) ? 8 : 0;
    int i0 = blockIdx.x << 7;
    int n0 = blockIdx.y << 7;

    int tid = threadIdx.x;
    int wid = tid >> 5, lane = tid & 31;
    int g = lane >> 2, tg = lane & 3;
    int wm = (wid & 1) * 64, wn = (wid >> 1) * 32;

    uint32_t baseA[4], baseB[2];
    uint32_t lrow = lane & 15, lcol = (lane >> 4) * 16;
#pragma unroll
    for (int mt = 0; mt < 4; mt++) baseA[mt] = swz((wm + mt * 16 + lrow) * 128 + lcol);
#pragma unroll
    for (int np = 0; np < 2; np++) baseB[np] = swz((wn + np * 16 + lrow) * 128 + lcol);

    const char* BB = (const char*)g_A + ((size_t)ob * CH + i0) * JD * 2;

    float acc[4][4][4];
#pragma unroll
    for (int a = 0; a < 4; a++)
#pragma unroll
        for (int b = 0; b < 4; b++)
#pragma unroll
            for (int c = 0; c < 4; c++) acc[a][b][c] = 0.f;

    const int NCH = JD / 64;   // 64

    auto load_chunk = [&](int c, int stg) {
        uint32_t s = sb + stg * STAGE_BYTES;
        int j0c = c * 64;
        int kvb = kvbase + (j0c >> 9);
        int jc0 = j0c & 511;
        const char* Ap = (const char*)g_V + (((size_t)kvb * NSEQ + n0) * CH + jc0) * 2;
        ldtile(s,         Ap, CH * 2, tid);
        ldtile(s + 16384, BB + (size_t)j0c * 2, JD * 2, tid);
        cp_commit();
    };

    load_chunk(0, 0);
    load_chunk(1, 1);
    for (int c = 0; c < NCH; c++) {
        if (c + 1 < NCH) cp_wait_group<1>(); else cp_wait_group<0>();
        __syncthreads();
        if (c + 2 < NCH) load_chunk(c + 2, (c + 2) % NSTG);
        uint32_t s = sb + (c % NSTG) * STAGE_BYTES;
        compute_stage(s, s + 16384, baseA, baseB, acc);
    }

    const float ds = 1.0f / SCALE_F;   // undo V pre-scale
    float* gout = g_CTX + (size_t)ob * NSEQ * CH;
#pragma unroll
    for (int mt = 0; mt < 4; mt++) {
#pragma unroll
        for (int nt = 0; nt < 4; nt++) {
            int row = n0 + wm + mt * 16 + g;
            int col = i0 + wn + nt * 8 + tg * 2;
            *(float2*)&gout[(size_t)row * CH + col] =
                make_float2(acc[mt][nt][0] * ds, acc[mt][nt][1] * ds);
            *(float2*)&gout[(size_t)(row + 8) * CH + col] =
                make_float2(acc[mt][nt][2] * ds, acc[mt][nt][3] * ds);
        }
    }
}

// ============================================================================
// fused QKV projection: Qt/Kt (transposed) + V (row) from one emb tile read.
// grid (CH/64=8, ROWS_TOT/64=512), 256 threads. Also zeroes g_red.
// ============================================================================
__global__ void __launch_bounds__(256) qkv_gemm(const float* __restrict__ A,
                                                const float* __restrict__ BmQ,
                                                const float* __restrict__ BmK,
                                                const float* __restrict__ BmV,
                                                __half* __restrict__ Qt,
                                                __half* __restrict__ Kt,
                                                __half* __restrict__ Vv) {
    __shared__ __align__(16) float As[16][68];
    __shared__ __align__(16) float BsQ[16][64], BsK[16][64], BsV[16][64];
    const int K = CDIM, N = CH;
    int bm = blockIdx.y * 64, bn = blockIdx.x * 64;
    int tid = threadIdx.x;

    if (blockIdx.x == 0 && blockIdx.y == 0 && tid < BTOT * 2)
        g_red[tid] = 0.0;

    int tx = tid & 15, ty = tid >> 4;
    int am = tid >> 2, ak = (tid & 3) << 2;
    int br = tid >> 4, bc = (tid & 15) << 2;
    const float* Aptr = A + (size_t)(bm + am) * K + ak;

    float aq[4][4], akk[4][4], av_[4][4];
#pragma unroll
    for (int i = 0; i < 4; i++)
#pragma unroll
        for (int j = 0; j < 4; j++) { aq[i][j] = 0.f; akk[i][j] = 0.f; av_[i][j] = 0.f; }

    for (int k0 = 0; k0 < K; k0 += 16) {
        float4 avv = *(const float4*)(Aptr + k0);
        As[ak + 0][am] = avv.x; As[ak + 1][am] = avv.y;
        As[ak + 2][am] = avv.z; As[ak + 3][am] = avv.w;
        size_t boff = (size_t)(k0 + br) * N + bn + bc;
        *(float4*)&BsQ[br][bc] = *(const float4*)&BmQ[boff];
        *(float4*)&BsK[br][bc] = *(const float4*)&BmK[boff];
        *(float4*)&BsV[br][bc] = *(const float4*)&BmV[boff];
        __syncthreads();
#pragma unroll
        for (int kk = 0; kk < 16; kk++) {
            float a0 = As[kk][ty * 4 + 0], a1 = As[kk][ty * 4 + 1];
            float a2 = As[kk][ty * 4 + 2], a3 = As[kk][ty * 4 + 3];
#pragma unroll
            for (int j = 0; j < 4; j++) {
                float bq = BsQ[kk][tx * 4 + j];
                float bk = BsK[kk][tx * 4 + j];
                float bv = BsV[kk][tx * 4 + j];
                aq[0][j] += a0 * bq; aq[1][j] += a1 * bq; aq[2][j] += a2 * bq; aq[3][j] += a3 * bq;
                akk[0][j] += a0 * bk; akk[1][j] += a1 * bk; akk[2][j] += a2 * bk; akk[3][j] += a3 * bk;
                av_[0][j] += a0 * bv; av_[1][j] += a1 * bv; av_[2][j] += a2 * bv; av_[3][j] += a3 * bv;
            }
        }
        __syncthreads();
    }

    // Qt / Kt transposed epilogue: out[b][col][n]
    {
        int b = bm >> 11;
        int nloc = (bm & 2047) + ty * 4;
#pragma unroll
        for (int j = 0; j < 4; j++) {
            int col = bn + tx * 4 + j;
            union { __half v[4]; uint2 u; } pq, pk;
#pragma unroll
            for (int i = 0; i < 4; i++) {
                pq.v[i] = __float2half(aq[i][j] * SCALE_F);
                pk.v[i] = __float2half(akk[i][j] * SCALE_F);
            }
            size_t off = (size_t)b * (CH * NSEQ) + (size_t)col * NSEQ + nloc;
            *(uint2*)&Qt[off] = pq.u;
            *(uint2*)&Kt[off] = pk.u;
        }
    }
    // V row-major epilogue
#pragma unroll
    for (int i = 0; i < 4; i++) {
        int m = bm + ty * 4 + i;
        union { __half v[4]; uint2 u; } pv;
#pragma unroll
        for (int j = 0; j < 4; j++)
            pv.v[j] = __float2half(av_[i][j] * SCALE_F);
        *(uint2*)&Vv[(size_t)m * CH + bn + tx * 4] = pv.u;
    }
}

// ============================================================================
// out projection fp32: C[M,64] = CTX[M,512] @ Wo[512,64]; 128x64 tile.
// ============================================================================
__global__ void __launch_bounds__(256) gemm_out(const float* __restrict__ A,
                                                const float* __restrict__ Bm,
                                                float* __restrict__ Cm) {
    __shared__ __align__(16) float As[16][132];
    __shared__ __align__(16) float Bs[16][64];
    const int K = CH, N = CDIM;
    int bm = blockIdx.x * 128;
    int tid = threadIdx.x;
    int tx = tid & 15, ty = tid >> 4;
    int am = tid >> 2, ak = (tid & 3) << 2;
    int br = tid >> 4, bc = (tid & 15) << 2;

    float acc[8][4];
#pragma unroll
    for (int i = 0; i < 8; i++)
#pragma unroll
        for (int j = 0; j < 4; j++) acc[i][j] = 0.f;

    for (int k0 = 0; k0 < K; k0 += 16) {
        float4 a0v = *(const float4*)&A[(size_t)(bm + am) * K + k0 + ak];
        float4 a1v = *(const float4*)&A[(size_t)(bm + am + 64) * K + k0 + ak];
        As[ak + 0][am] = a0v.x; As[ak + 1][am] = a0v.y;
        As[ak + 2][am] = a0v.z; As[ak + 3][am] = a0v.w;
        As[ak + 0][am + 64] = a1v.x; As[ak + 1][am + 64] = a1v.y;
        As[ak + 2][am + 64] = a1v.z; As[ak + 3][am + 64] = a1v.w;
        *(float4*)&Bs[br][bc] = *(const float4*)&Bm[(size_t)(k0 + br) * N + bc];
        __syncthreads();
#pragma unroll
        for (int kk = 0; kk < 16; kk++) {
            float a[8], b[4];
            *(float4*)&a[0] = *(float4*)&As[kk][ty * 8];
            *(float4*)&a[4] = *(float4*)&As[kk][ty * 8 + 4];
            *(float4*)&b[0] = *(float4*)&Bs[kk][tx * 4];
#pragma unroll
            for (int i = 0; i < 8; i++)
#pragma unroll
                for (int j = 0; j < 4; j++) acc[i][j] += a[i] * b[j];
        }
        __syncthreads();
    }
#pragma unroll
    for (int i = 0; i < 8; i++) {
        float4 v = make_float4(acc[i][0], acc[i][1], acc[i][2], acc[i][3]);
        *(float4*)&Cm[(size_t)(bm + ty * 8 + i) * N + tx * 4] = v;
    }
}

// ============================================================================
// softmax (fused rstd finalize): scale + softmax over j, write attn fp16.
// ============================================================================
__global__ void __launch_bounds__(256) softmax_k() {
    int row = blockIdx.x;
    int b = row >> 9;
    __shared__ float srstd;
    __shared__ float red[8];
    int t = threadIdx.x;

    if (t == 0) {
        const double SC = 65536.0;   // scores are scaled by 2^16
        double n = (double)CH * (double)JD;
        double mean = g_red[2 * b] / (n * SC);
        double var  = g_red[2 * b + 1] / (n * SC * SC) - mean * mean;
        srstd = rsqrtf((float)var + EPS_F) / (float)SC;
    }

    const float* p = g_S + (size_t)row * JD;
    float4 xv[4];
#pragma unroll
    for (int u = 0; u < 4; u++)
        xv[u] = *(const float4*)&p[u * 1024 + t * 4];
    __syncthreads();
    float rstd = srstd;

    float* x = (float*)xv;
    float mx = -1e30f;
#pragma unroll
    for (int u = 0; u < 16; u++) {
        x[u] *= rstd;
        mx = fmaxf(mx, x[u]);
    }
    for (int off = 16; off > 0; off >>= 1)
        mx = fmaxf(mx, __shfl_xor_sync(0xffffffffu, mx, off));
    int lane = t & 31, wid = t >> 5;
    if (lane == 0) red[wid] = mx;
    __syncthreads();
    float gm = red[0];
#pragma unroll
    for (int w = 1; w < 8; w++) gm = fmaxf(gm, red[w]);
    __syncthreads();

    float sum = 0.f;
#pragma unroll
    for (int u = 0; u < 16; u++) {
        x[u] = __expf(x[u] - gm);
        sum += x[u];
    }
    for (int off = 16; off > 0; off >>= 1)
        sum += __shfl_xor_sync(0xffffffffu, sum, off);
    if (lane == 0) red[wid] = sum;
    __syncthreads();
    float tot = 0.f;
#pragma unroll
    for (int w = 0; w < 8; w++) tot += red[w];
    float inv = 1.0f / tot;

    __half* ah = g_A + (size_t)row * JD;
#pragma unroll
    for (int u = 0; u < 4; u++) {
        union { __half v[4]; uint2 q; } pk;
#pragma unroll
        for (int e = 0; e < 4; e++)
            pk.v[e] = __float2half(x[u * 4 + e] * inv);
        *(uint2*)&ah[u * 1024 + t * 4] = pk.q;
    }
}

// ============================================================================
// launch
// ============================================================================
extern "C" void kernel_launch(void* const* d_in, const int* in_sizes, int n_in,
                              void* d_out, int out_size) {
    const float* emb = (const float*)d_in[0];
    const float* Wq  = (const float*)d_in[1];
    const float* Wk  = (const float*)d_in[2];
    const float* Wv  = (const float*)d_in[3];
    const float* Wo  = (const float*)d_in[4];
    float* outp = (float*)d_out;

    void *qt, *kt, *vv, *cx;
    cudaGetSymbolAddress(&qt, g_Qt);
    cudaGetSymbolAddress(&kt, g_Kt);
    cudaGetSymbolAddress(&vv, g_V);
    cudaGetSymbolAddress(&cx, g_CTX);

    cudaFuncSetAttribute(scores_mma, cudaFuncAttributeMaxDynamicSharedMemorySize, SMEM_DYN);
    cudaFuncSetAttribute(ctx_mma, cudaFuncAttributeMaxDynamicSharedMemorySize, SMEM_DYN);

    qkv_gemm<<<dim3(CH / 64, ROWS_TOT / 64), 256>>>(emb, Wq, Wk, Wv,
                                                    (__half*)qt, (__half*)kt, (__half*)vv);

    scores_mma<<<dim3(JD / 128, CH / 128, BTOT), 256, SMEM_DYN>>>();

    softmax_k<<<BTOT * CH, 256>>>();

    ctx_mma<<<dim3(CH / 128, NSEQ / 128, BTOT), 256, SMEM_DYN>>>();

    gemm_out<<<ROWS_TOT / 128, 256>>>((const float*)cx, Wo, outp);
}